// round 4
// baseline (speedup 1.0000x reference)
#include <cuda_runtime.h>

// Problem constants (fixed shapes from setup_inputs)
#define BD 2
#define FD 32
#define CD 5
#define DHW 884736           // 96*96*96
#define Q4 (DHW/4)           // 221184
#define NVOX (BD*DHW)        // 1769472
#define NG (NVOX/4)          // 442368
#define NFEAT (BD*FD*DHW)    // 56623104
#define PLO 15872            // smem-privatized prefix range for level-1 hist
#define NPRE 448             // covers float prefixes of conf in [0.125, 1.007)
#define NSLOT 20             // 5 classes x 4 order statistics (lo_i, lo_i+1, hi_i, hi_i+1)

// ---------------- device scratch (static: no allocations allowed) ----------------
__device__ __align__(16) float g_conf[NVOX];
__device__ unsigned int g_hist1[CD * 65536];
__device__ unsigned int g_seg1[CD * 1024];
__device__ unsigned int g_hist2[NSLOT * 256];
__device__ unsigned int g_hist3[NSLOT * 256];
__device__ int          g_t2_pre[NSLOT];    // 16-bit prefix per slot (-1 = class empty)
__device__ unsigned int g_t2_rank[NSLOT];   // rank within prefix bin
__device__ int          g_t3_byte[NSLOT];   // byte[15:8]
__device__ unsigned int g_t3_rank[NSLOT];
__device__ unsigned int g_xbits[NSLOT];     // exact order-statistic float bits
__device__ unsigned int g_n[CD];
__device__ double       g_g05[CD], g_g95[CD];
__device__ float        g_newmin[CD], g_newmax[CD];

// ---------------- K0: zero histograms (must run every graph replay) ----------------
__global__ void k_zero() {
    int i = blockIdx.x * blockDim.x + threadIdx.x;
    int stride = gridDim.x * blockDim.x;
    for (int j = i; j < CD * 65536; j += stride) g_hist1[j] = 0;
    for (int j = i; j < NSLOT * 256; j += stride) { g_hist2[j] = 0; g_hist3[j] = 0; }
}

// ---------------- K1: confidence map + level-1 histogram (smem privatized) --------
__device__ __forceinline__ float conf5(float a, float b, float c, float d, float e) {
    float y0 = a * 10.0f, y1 = b * 10.0f, y2 = c * 10.0f, y3 = d * 10.0f, y4 = e * 10.0f;
    float m = fmaxf(fmaxf(fmaxf(y0, y1), fmaxf(y2, y3)), y4);
    float s = expf(y0 - m) + expf(y1 - m) + expf(y2 - m) + expf(y3 - m) + expf(y4 - m);
    return 1.0f / s;
}

__global__ void k_conf(const float4* __restrict__ lg, const int4* __restrict__ lb) {
    __shared__ unsigned int sh[CD * NPRE];
    for (int j = threadIdx.x; j < CD * NPRE; j += blockDim.x) sh[j] = 0;
    __syncthreads();
    int stride = gridDim.x * blockDim.x;
    for (int g = blockIdx.x * blockDim.x + threadIdx.x; g < NG; g += stride) {
        int v = g * 4;
        int b = (v >= DHW) ? 1 : 0;
        int s4 = g - b * Q4;
        size_t base = (size_t)(b * CD) * Q4 + (size_t)s4;
        float4 L0 = lg[base];
        float4 L1 = lg[base + Q4];
        float4 L2 = lg[base + 2 * (size_t)Q4];
        float4 L3 = lg[base + 3 * (size_t)Q4];
        float4 L4 = lg[base + 4 * (size_t)Q4];
        float c0 = conf5(L0.x, L1.x, L2.x, L3.x, L4.x);
        float c1 = conf5(L0.y, L1.y, L2.y, L3.y, L4.y);
        float c2 = conf5(L0.z, L1.z, L2.z, L3.z, L4.z);
        float c3 = conf5(L0.w, L1.w, L2.w, L3.w, L4.w);
        ((float4*)g_conf)[g] = make_float4(c0, c1, c2, c3);
        int4 li = lb[g];
        {
            unsigned k = __float_as_uint(c0); int p = (int)(k >> 16);
            if ((unsigned)(p - PLO) < NPRE) atomicAdd(&sh[li.x * NPRE + (p - PLO)], 1u);
            else atomicAdd(&g_hist1[li.x * 65536 + p], 1u);
        }
        {
            unsigned k = __float_as_uint(c1); int p = (int)(k >> 16);
            if ((unsigned)(p - PLO) < NPRE) atomicAdd(&sh[li.y * NPRE + (p - PLO)], 1u);
            else atomicAdd(&g_hist1[li.y * 65536 + p], 1u);
        }
        {
            unsigned k = __float_as_uint(c2); int p = (int)(k >> 16);
            if ((unsigned)(p - PLO) < NPRE) atomicAdd(&sh[li.z * NPRE + (p - PLO)], 1u);
            else atomicAdd(&g_hist1[li.z * 65536 + p], 1u);
        }
        {
            unsigned k = __float_as_uint(c3); int p = (int)(k >> 16);
            if ((unsigned)(p - PLO) < NPRE) atomicAdd(&sh[li.w * NPRE + (p - PLO)], 1u);
            else atomicAdd(&g_hist1[li.w * 65536 + p], 1u);
        }
    }
    __syncthreads();
    for (int j = threadIdx.x; j < CD * NPRE; j += blockDim.x) {
        unsigned u = sh[j];
        if (u) atomicAdd(&g_hist1[(j / NPRE) * 65536 + PLO + (j % NPRE)], u);
    }
}

// ---------------- K2a: 64-bin segment sums of hist1 (coalesced, warp/segment) -----
__global__ void k_seg() {
    int warp = (blockIdx.x * blockDim.x + threadIdx.x) >> 5;
    int lane = threadIdx.x & 31;
    if (warp >= CD * 1024) return;
    unsigned s = g_hist1[warp * 64 + lane] + g_hist1[warp * 64 + 32 + lane];
    for (int off = 16; off; off >>= 1) s += __shfl_down_sync(0xffffffffu, s, off);
    if (lane == 0) g_seg1[warp] = s;
}

// ---------------- K2b: scan segments, compute quantile ranks, find L2 targets -----
__global__ void k_find2() {  // 1 block, 1024 threads
    __shared__ unsigned int s_scan[1024];
    __shared__ unsigned int s_seg[1024];
    int t = threadIdx.x;
    for (int c = 0; c < CD; c++) {
        unsigned sum = g_seg1[c * 1024 + t];
        s_seg[t] = sum; s_scan[t] = sum;
        __syncthreads();
        for (int off = 1; off < 1024; off <<= 1) {
            unsigned add = (t >= off) ? s_scan[t - off] : 0;
            __syncthreads();
            s_scan[t] += add;
            __syncthreads();
        }
        unsigned total = s_scan[1023];
        unsigned excl = s_scan[t] - s_seg[t];
        if (t == 0) g_n[c] = total;
        long long n = (long long)total;
        if (n == 0) {
            if (t < 4) g_t2_pre[c * 4 + t] = -1;
            if (t == 0) { g_g05[c] = 0.0; g_g95[c] = 0.0; }
        } else {
            double p05 = 0.05 * (double)(n - 1);
            long long i05 = (long long)p05; double f05 = p05 - (double)i05;
            double p95 = 0.95 * (double)(n - 1);
            long long i95 = (long long)p95; double f95 = p95 - (double)i95;
            if (t == 0) { g_g05[c] = f05; g_g95[c] = f95; }
            long long rr[4];
            rr[0] = i05; rr[1] = (i05 + 1 < n) ? i05 + 1 : i05;
            rr[2] = i95; rr[3] = (i95 + 1 < n) ? i95 + 1 : i95;
            for (int j = 0; j < 4; j++) {
                long long r = rr[j];
                if ((long long)excl <= r && r < (long long)excl + (long long)s_seg[t]) {
                    unsigned rem = (unsigned)(r - (long long)excl);
                    unsigned run = 0;
                    for (int k2 = 0; k2 < 64; k2++) {
                        unsigned h = g_hist1[c * 65536 + t * 64 + k2];
                        if (rem < run + h) {
                            g_t2_pre[c * 4 + j] = t * 64 + k2;
                            g_t2_rank[c * 4 + j] = rem - run;
                            break;
                        }
                        run += h;
                    }
                }
            }
        }
        __syncthreads();
    }
}

// ---------------- K3: level-2 histogram (byte[15:8]) within target prefixes -------
__global__ void k_hist2(const int* __restrict__ lab) {
    __shared__ unsigned int sh[NSLOT * 256];
    __shared__ int sp[NSLOT];
    __shared__ int sskip[NSLOT];
    for (int j = threadIdx.x; j < NSLOT * 256; j += blockDim.x) sh[j] = 0;
    if (threadIdx.x < NSLOT) sp[threadIdx.x] = g_t2_pre[threadIdx.x];
    __syncthreads();
    if (threadIdx.x < NSLOT) {
        int w = threadIdx.x;
        sskip[w] = ((w & 1) && sp[w] >= 0 && sp[w] == sp[w - 1]) ? 1 : 0;
    }
    __syncthreads();
    int stride = gridDim.x * blockDim.x;
    for (int v = blockIdx.x * blockDim.x + threadIdx.x; v < NVOX; v += stride) {
        int c = lab[v];
        unsigned k = __float_as_uint(g_conf[v]);
        int p = (int)(k >> 16);
        int b1 = (int)((k >> 8) & 255u);
        int base = c * 4;
#pragma unroll
        for (int s = 0; s < 4; s++) {
            int slot = base + s;
            if (!sskip[slot] && sp[slot] == p) atomicAdd(&sh[slot * 256 + b1], 1u);
        }
    }
    __syncthreads();
    for (int j = threadIdx.x; j < NSLOT * 256; j += blockDim.x) {
        unsigned u = sh[j];
        if (u) atomicAdd(&g_hist2[j], u);
    }
}

// ---------------- K4: locate byte[15:8] per slot from hist2 (warp per slot) -------
__global__ void k_find3() {  // 1 block, 640 threads (20 warps)
    int t = threadIdx.x; int w = t >> 5, l = t & 31;
    int pre = g_t2_pre[w];
    if (pre < 0) { if (l == 0) g_t3_byte[w] = -1; return; }
    int src = w;
    if ((w & 1) && pre == g_t2_pre[w - 1]) src = w - 1;
    unsigned rank = g_t2_rank[w];
    unsigned h[8]; unsigned sum = 0;
#pragma unroll
    for (int j = 0; j < 8; j++) { h[j] = g_hist2[src * 256 + l * 8 + j]; sum += h[j]; }
    unsigned v = sum;
    for (int off = 1; off < 32; off <<= 1) {
        unsigned u = __shfl_up_sync(0xffffffffu, v, off);
        if (l >= off) v += u;
    }
    unsigned excl = v - sum;
    if (excl <= rank && rank < excl + sum) {
        unsigned run = excl;
#pragma unroll
        for (int j = 0; j < 8; j++) {
            if (rank < run + h[j]) { g_t3_byte[w] = l * 8 + j; g_t3_rank[w] = rank - run; break; }
            run += h[j];
        }
    }
}

// ---------------- K5: level-3 histogram (byte[7:0]) -------------------------------
__global__ void k_hist3(const int* __restrict__ lab) {
    __shared__ unsigned int sh[NSLOT * 256];
    __shared__ int sp[NSLOT];
    __shared__ int sb[NSLOT];
    __shared__ int sskip[NSLOT];
    for (int j = threadIdx.x; j < NSLOT * 256; j += blockDim.x) sh[j] = 0;
    if (threadIdx.x < NSLOT) {
        sp[threadIdx.x] = g_t2_pre[threadIdx.x];
        sb[threadIdx.x] = g_t3_byte[threadIdx.x];
    }
    __syncthreads();
    if (threadIdx.x < NSLOT) {
        int w = threadIdx.x;
        sskip[w] = ((w & 1) && sp[w] >= 0 && sp[w] == sp[w - 1] && sb[w] == sb[w - 1]) ? 1 : 0;
    }
    __syncthreads();
    int stride = gridDim.x * blockDim.x;
    for (int v = blockIdx.x * blockDim.x + threadIdx.x; v < NVOX; v += stride) {
        int c = lab[v];
        unsigned k = __float_as_uint(g_conf[v]);
        int p = (int)(k >> 16);
        int b1 = (int)((k >> 8) & 255u);
        int b0 = (int)(k & 255u);
        int base = c * 4;
#pragma unroll
        for (int s = 0; s < 4; s++) {
            int slot = base + s;
            if (!sskip[slot] && sp[slot] == p && sb[slot] == b1) atomicAdd(&sh[slot * 256 + b0], 1u);
        }
    }
    __syncthreads();
    for (int j = threadIdx.x; j < NSLOT * 256; j += blockDim.x) {
        unsigned u = sh[j];
        if (u) atomicAdd(&g_hist3[j], u);
    }
}

// ---------------- K6: exact order statistics -> quantiles -> EMA ------------------
__global__ void k_final(const float* __restrict__ emin, const float* __restrict__ emax,
                        const unsigned char* __restrict__ einit) {  // 1 block, 640 threads
    int t = threadIdx.x; int w = t >> 5, l = t & 31;
    int pre = g_t2_pre[w];
    if (pre >= 0) {
        int byt = g_t3_byte[w];
        int src = w;
        if ((w & 1) && pre == g_t2_pre[w - 1] && byt == g_t3_byte[w - 1]) src = w - 1;
        unsigned rank = g_t3_rank[w];
        unsigned h[8]; unsigned sum = 0;
#pragma unroll
        for (int j = 0; j < 8; j++) { h[j] = g_hist3[src * 256 + l * 8 + j]; sum += h[j]; }
        unsigned v = sum;
        for (int off = 1; off < 32; off <<= 1) {
            unsigned u = __shfl_up_sync(0xffffffffu, v, off);
            if (l >= off) v += u;
        }
        unsigned excl = v - sum;
        if (excl <= rank && rank < excl + sum) {
            unsigned run = excl;
#pragma unroll
            for (int j = 0; j < 8; j++) {
                if (rank < run + h[j]) {
                    g_xbits[w] = ((unsigned)pre << 16) | ((unsigned)byt << 8) | (unsigned)(l * 8 + j);
                    break;
                }
                run += h[j];
            }
        }
    }
    __syncthreads();
    if (t < CD) {
        int c = t;
        float nmin, nmax;
        if (g_n[c] == 0) {
            nmin = emin[c]; nmax = emax[c];   // has_vox == false -> keep old EMA
        } else {
            float x0 = __uint_as_float(g_xbits[c * 4 + 0]);
            float x1 = __uint_as_float(g_xbits[c * 4 + 1]);
            float x2 = __uint_as_float(g_xbits[c * 4 + 2]);
            float x3 = __uint_as_float(g_xbits[c * 4 + 3]);
            float bmin = (float)((double)x0 + g_g05[c] * ((double)x1 - (double)x0));
            float bmax = (float)((double)x2 + g_g95[c] * ((double)x3 - (double)x2));
            bool ini = einit[c] != 0;
            nmin = ini ? (0.99f * emin[c] + 0.01f * bmin) : bmin;
            nmax = ini ? (0.99f * emax[c] + 0.01f * bmax) : bmax;
        }
        g_newmin[c] = nmin; g_newmax[c] = nmax;
    }
}

// ---------------- K7: gamma map + feature scaling (HBM-bound) ---------------------
__global__ void k_scale(const float4* __restrict__ ft, const int4* __restrict__ lb,
                        const float* __restrict__ ranks, float* __restrict__ out) {
    __shared__ float smin[CD], sinv[CD], sadd[CD], smax[CD], sint[CD];
    if (threadIdx.x < CD) {
        int c = threadIdx.x;
        float mn = g_newmin[c], mx = g_newmax[c];
        smin[c] = mn; smax[c] = mx;
        sint[c] = 1.0f - ranks[c] / 4.0f;   // 1 - rank/(C-1)
        if (mx > mn) { sinv[c] = 1.0f / (mx - mn + 1e-8f); sadd[c] = 0.0f; }
        else         { sinv[c] = 0.0f;                     sadd[c] = 0.5f; }
    }
    __syncthreads();
    int g = blockIdx.x * blockDim.x + threadIdx.x;
    if (g >= NG) return;
    int4 li = lb[g];
    float4 cf = ((const float4*)g_conf)[g];

    float gm[4];
    {
        int cc[4] = {li.x, li.y, li.z, li.w};
        float cv[4] = {cf.x, cf.y, cf.z, cf.w};
#pragma unroll
        for (int k = 0; k < 4; k++) {
            int c = cc[k];
            float mn = smin[c], mx = smax[c];
            float cl = fminf(fmaxf(cv[k], mn), mx);
            float nr = (cl - mn) * sinv[c] + sadd[c];
            gm[k] = 1.0f + sint[c] * (1.0f + 0.5f * (1.0f - nr));
        }
    }
    ((float4*)(out + NFEAT))[g] = make_float4(gm[0], gm[1], gm[2], gm[3]);

    int v = g * 4;
    int b = (v >= DHW) ? 1 : 0;
    int s4 = g - b * Q4;
    size_t fbase = (size_t)(b * FD) * Q4 + (size_t)s4;
    float4* o4 = (float4*)out;
#pragma unroll 8
    for (int f = 0; f < FD; f++) {
        float4 x = ft[fbase + (size_t)f * Q4];
        x.x *= gm[0]; x.y *= gm[1]; x.z *= gm[2]; x.w *= gm[3];
        o4[fbase + (size_t)f * Q4] = x;
    }
}

// ---------------- launch ----------------------------------------------------------
extern "C" void kernel_launch(void* const* d_in, const int* in_sizes, int n_in,
                              void* d_out, int out_size) {
    const float* feat          = (const float*)d_in[0];
    const float* logits        = (const float*)d_in[1];
    const int*   labels        = (const int*)d_in[2];
    const float* ranks         = (const float*)d_in[3];
    const float* emin          = (const float*)d_in[4];
    const float* emax          = (const float*)d_in[5];
    const unsigned char* einit = (const unsigned char*)d_in[6];
    float* out = (float*)d_out;
    (void)in_sizes; (void)n_in; (void)out_size;

    k_zero<<<256, 256>>>();
    k_conf<<<296, 256>>>((const float4*)logits, (const int4*)labels);
    k_seg<<<640, 256>>>();
    k_find2<<<1, 1024>>>();
    k_hist2<<<296, 256>>>(labels);
    k_find3<<<1, 640>>>();
    k_hist3<<<296, 256>>>(labels);
    k_final<<<1, 640>>>(emin, emax, einit);
    k_scale<<<(NG + 255) / 256, 256>>>((const float4*)feat, (const int4*)labels, ranks, out);
}

// round 5
// speedup vs baseline: 1.1978x; 1.1978x over previous
#include <cuda_runtime.h>

// Fixed problem shapes
#define BD 2
#define FD 32
#define CD 5
#define DHW 884736           // 96^3
#define Q4 (DHW/4)           // 221184
#define NVOX (BD*DHW)        // 1769472
#define NG (NVOX/4)          // 442368
#define NFEAT (BD*FD*DHW)    // 56623104
#define PLO 15872            // conf in (0.125,1.0] -> 16-bit prefix in [15948,16256] subset of [PLO,PLO+512)
#define NBIN 512
#define NSLOT 20             // 5 classes x 4 order statistics

// ---------------- device scratch (no allocations allowed) ----------------
__device__ __align__(16) unsigned g_packed[NVOX];   // label<<29 | (conf bits & 0x1FFFFFFF)
__device__ unsigned g_hist1[CD * NBIN];
__device__ unsigned g_hist2[NSLOT * 256];
__device__ unsigned g_hist3[NSLOT * 256];
__device__ int      g_t2_pre[NSLOT];
__device__ unsigned g_t2_rank[NSLOT];
__device__ int      g_t3_byte[NSLOT];
__device__ unsigned g_t3_rank[NSLOT];
__device__ unsigned g_xbits[NSLOT];
__device__ unsigned g_n[CD];
__device__ double   g_g05[CD], g_g95[CD];
__device__ float    g_newmin[CD], g_newmax[CD];

__device__ __forceinline__ unsigned unpack_bits(unsigned pk) {
    return (pk & 0x1FFFFFFFu) | 0x20000000u;   // restore constant top bits of conf float
}

// ---------------- K0: zero histograms ----------------
__global__ void k_zero() {
    int i = blockIdx.x * blockDim.x + threadIdx.x;
    int stride = gridDim.x * blockDim.x;
    for (int j = i; j < CD * NBIN; j += stride) g_hist1[j] = 0;
    for (int j = i; j < NSLOT * 256; j += stride) { g_hist2[j] = 0; g_hist3[j] = 0; }
}

// ---------------- K1: confidence + packed store + level-1 histogram ----------------
__device__ __forceinline__ float conf5(float a, float b, float c, float d, float e) {
    float y0 = a * 10.0f, y1 = b * 10.0f, y2 = c * 10.0f, y3 = d * 10.0f, y4 = e * 10.0f;
    float m = fmaxf(fmaxf(fmaxf(y0, y1), fmaxf(y2, y3)), y4);
    float s = expf(y0 - m) + expf(y1 - m) + expf(y2 - m) + expf(y3 - m) + expf(y4 - m);
    return 1.0f / s;
}

__global__ void k_conf(const float4* __restrict__ lg, const int4* __restrict__ lb) {
    __shared__ unsigned sh[CD * NBIN];
    for (int j = threadIdx.x; j < CD * NBIN; j += blockDim.x) sh[j] = 0;
    __syncthreads();
    int stride = gridDim.x * blockDim.x;
    for (int g = blockIdx.x * blockDim.x + threadIdx.x; g < NG; g += stride) {
        int v = g * 4;
        int b = (v >= DHW) ? 1 : 0;
        int s4 = g - b * Q4;
        size_t base = (size_t)(b * CD) * Q4 + (size_t)s4;
        float4 L0 = lg[base];
        float4 L1 = lg[base + Q4];
        float4 L2 = lg[base + 2 * (size_t)Q4];
        float4 L3 = lg[base + 3 * (size_t)Q4];
        float4 L4 = lg[base + 4 * (size_t)Q4];
        float cf[4];
        cf[0] = conf5(L0.x, L1.x, L2.x, L3.x, L4.x);
        cf[1] = conf5(L0.y, L1.y, L2.y, L3.y, L4.y);
        cf[2] = conf5(L0.z, L1.z, L2.z, L3.z, L4.z);
        cf[3] = conf5(L0.w, L1.w, L2.w, L3.w, L4.w);
        int4 li = lb[g];
        int cc[4] = { li.x, li.y, li.z, li.w };
        unsigned pk[4];
#pragma unroll
        for (int k = 0; k < 4; k++) {
            unsigned bits = __float_as_uint(cf[k]);
            pk[k] = ((unsigned)cc[k] << 29) | (bits & 0x1FFFFFFFu);
            unsigned idx = (bits >> 16) - PLO;
            if (idx < NBIN) atomicAdd(&sh[cc[k] * NBIN + idx], 1u);
        }
        ((uint4*)g_packed)[g] = make_uint4(pk[0], pk[1], pk[2], pk[3]);
    }
    __syncthreads();
    for (int j = threadIdx.x; j < CD * NBIN; j += blockDim.x) {
        unsigned u = sh[j];
        if (u) atomicAdd(&g_hist1[j], u);
    }
}

// ---------------- K2: fused find2 prologue + level-2 histogram ----------------
__global__ void k_hist2() {
    __shared__ unsigned shh[NSLOT * 256];
    __shared__ int   spre[NSLOT];
    __shared__ unsigned srank[NSLOT];
    __shared__ int   sskip[NSLOT];
    __shared__ unsigned swsum[8], swpre[8];
    __shared__ unsigned s_n;

    int t = threadIdx.x, lane = t & 31, warp = t >> 5;
    if (t < NSLOT) { spre[t] = -1; srank[t] = 0; }
    __syncthreads();

    // ---- find2: per-class scan of the 512-bin prefix histogram ----
    for (int c = 0; c < CD; c++) {
        unsigned a = g_hist1[c * NBIN + 2 * t];
        unsigned b = g_hist1[c * NBIN + 2 * t + 1];
        unsigned s = a + b;
        unsigned incl = s;
        for (int off = 1; off < 32; off <<= 1) {
            unsigned u = __shfl_up_sync(0xffffffffu, incl, off);
            if (lane >= off) incl += u;
        }
        if (lane == 31) swsum[warp] = incl;
        __syncthreads();
        if (t == 0) {
            unsigned run = 0;
#pragma unroll
            for (int w = 0; w < 8; w++) { swpre[w] = run; run += swsum[w]; }
            s_n = run;
        }
        __syncthreads();
        unsigned total = s_n;
        long long exclp = (long long)(incl - s + swpre[warp]);
        long long n = (long long)total;
        if (n == 0) {
            if (t == 0 && blockIdx.x == 0) { g_n[c] = 0; g_g05[c] = 0.0; g_g95[c] = 0.0; }
        } else {
            double p05 = 0.05 * (double)(n - 1);
            long long i05 = (long long)p05;
            double p95 = 0.95 * (double)(n - 1);
            long long i95 = (long long)p95;
            if (t == 0 && blockIdx.x == 0) {
                g_n[c] = total;
                g_g05[c] = p05 - (double)i05;
                g_g95[c] = p95 - (double)i95;
            }
            long long rr[4];
            rr[0] = i05; rr[1] = (i05 + 1 < n) ? i05 + 1 : i05;
            rr[2] = i95; rr[3] = (i95 + 1 < n) ? i95 + 1 : i95;
#pragma unroll
            for (int j = 0; j < 4; j++) {
                long long r = rr[j];
                if (r >= exclp && r < exclp + (long long)s) {
                    unsigned rem = (unsigned)(r - exclp);
                    if (rem < a) { spre[c * 4 + j] = PLO + 2 * t;     srank[c * 4 + j] = rem; }
                    else         { spre[c * 4 + j] = PLO + 2 * t + 1; srank[c * 4 + j] = rem - a; }
                }
            }
        }
        __syncthreads();
    }
    if (t < NSLOT) {
        sskip[t] = ((t & 1) && spre[t] >= 0 && spre[t] == spre[t - 1]) ? 1 : 0;
        if (blockIdx.x == 0) { g_t2_pre[t] = spre[t]; g_t2_rank[t] = srank[t]; }
    }
    for (int j = t; j < NSLOT * 256; j += blockDim.x) shh[j] = 0;
    __syncthreads();

    // ---- level-2 histogram over packed stream ----
    int stride = gridDim.x * blockDim.x;
    for (int g = blockIdx.x * blockDim.x + t; g < NG; g += stride) {
        uint4 p4 = ((const uint4*)g_packed)[g];
        unsigned pks[4] = { p4.x, p4.y, p4.z, p4.w };
#pragma unroll
        for (int k = 0; k < 4; k++) {
            unsigned pk = pks[k];
            int c = (int)(pk >> 29);
            unsigned bits = unpack_bits(pk);
            int p = (int)(bits >> 16);
            int b1 = (int)((bits >> 8) & 255u);
            int base = c * 4;
#pragma unroll
            for (int s = 0; s < 4; s++) {
                int slot = base + s;
                if (!sskip[slot] && spre[slot] == p) atomicAdd(&shh[slot * 256 + b1], 1u);
            }
        }
    }
    __syncthreads();
    for (int j = t; j < NSLOT * 256; j += blockDim.x) {
        unsigned u = shh[j];
        if (u) atomicAdd(&g_hist2[j], u);
    }
}

// ---------------- K3: fused find3 prologue + level-3 histogram ----------------
__global__ void k_hist3() {
    __shared__ unsigned shh[NSLOT * 256];
    __shared__ int   sp[NSLOT];
    __shared__ int   sb[NSLOT];
    __shared__ unsigned sr[NSLOT];
    __shared__ int   sskip[NSLOT];

    int t = threadIdx.x, lane = t & 31, warp = t >> 5;
    if (t < NSLOT) { sp[t] = g_t2_pre[t]; sb[t] = -1; sr[t] = 0; }
    __syncthreads();

    // ---- find3: warp per slot, locate byte[15:8] ----
    for (int slot = warp; slot < NSLOT; slot += 8) {
        int pre = sp[slot];
        if (pre < 0) continue;
        int src = slot;
        if ((slot & 1) && pre == sp[slot - 1]) src = slot - 1;
        unsigned rank = g_t2_rank[slot];
        unsigned h[8]; unsigned sum = 0;
#pragma unroll
        for (int j = 0; j < 8; j++) { h[j] = g_hist2[src * 256 + lane * 8 + j]; sum += h[j]; }
        unsigned v = sum;
        for (int off = 1; off < 32; off <<= 1) {
            unsigned u = __shfl_up_sync(0xffffffffu, v, off);
            if (lane >= off) v += u;
        }
        unsigned excl = v - sum;
        if (excl <= rank && rank < excl + sum) {
            unsigned run = excl;
#pragma unroll
            for (int j = 0; j < 8; j++) {
                if (rank < run + h[j]) { sb[slot] = lane * 8 + j; sr[slot] = rank - run; break; }
                run += h[j];
            }
        }
    }
    __syncthreads();
    if (t < NSLOT) {
        sskip[t] = ((t & 1) && sp[t] >= 0 && sp[t] == sp[t - 1] && sb[t] == sb[t - 1]) ? 1 : 0;
        if (blockIdx.x == 0) { g_t3_byte[t] = sb[t]; g_t3_rank[t] = sr[t]; }
    }
    for (int j = t; j < NSLOT * 256; j += blockDim.x) shh[j] = 0;
    __syncthreads();

    // ---- level-3 histogram ----
    int stride = gridDim.x * blockDim.x;
    for (int g = blockIdx.x * blockDim.x + t; g < NG; g += stride) {
        uint4 p4 = ((const uint4*)g_packed)[g];
        unsigned pks[4] = { p4.x, p4.y, p4.z, p4.w };
#pragma unroll
        for (int k = 0; k < 4; k++) {
            unsigned pk = pks[k];
            int c = (int)(pk >> 29);
            unsigned bits = unpack_bits(pk);
            int p = (int)(bits >> 16);
            int b1 = (int)((bits >> 8) & 255u);
            int b0 = (int)(bits & 255u);
            int base = c * 4;
#pragma unroll
            for (int s = 0; s < 4; s++) {
                int slot = base + s;
                if (!sskip[slot] && sp[slot] == p && sb[slot] == b1) atomicAdd(&shh[slot * 256 + b0], 1u);
            }
        }
    }
    __syncthreads();
    for (int j = t; j < NSLOT * 256; j += blockDim.x) {
        unsigned u = shh[j];
        if (u) atomicAdd(&g_hist3[j], u);
    }
}

// ---------------- K4: exact order statistics -> quantiles -> EMA ----------------
__global__ void k_final(const float* __restrict__ emin, const float* __restrict__ emax,
                        const unsigned char* __restrict__ einit) {  // 1 block, 640 threads
    int t = threadIdx.x; int w = t >> 5, l = t & 31;
    int pre = g_t2_pre[w];
    if (pre >= 0) {
        int byt = g_t3_byte[w];
        int src = w;
        if ((w & 1) && pre == g_t2_pre[w - 1] && byt == g_t3_byte[w - 1]) src = w - 1;
        unsigned rank = g_t3_rank[w];
        unsigned h[8]; unsigned sum = 0;
#pragma unroll
        for (int j = 0; j < 8; j++) { h[j] = g_hist3[src * 256 + l * 8 + j]; sum += h[j]; }
        unsigned v = sum;
        for (int off = 1; off < 32; off <<= 1) {
            unsigned u = __shfl_up_sync(0xffffffffu, v, off);
            if (l >= off) v += u;
        }
        unsigned excl = v - sum;
        if (excl <= rank && rank < excl + sum) {
            unsigned run = excl;
#pragma unroll
            for (int j = 0; j < 8; j++) {
                if (rank < run + h[j]) {
                    g_xbits[w] = ((unsigned)pre << 16) | ((unsigned)byt << 8) | (unsigned)(l * 8 + j);
                    break;
                }
                run += h[j];
            }
        }
    }
    __syncthreads();
    if (t < CD) {
        int c = t;
        float nmin, nmax;
        if (g_n[c] == 0) {
            nmin = emin[c]; nmax = emax[c];
        } else {
            float x0 = __uint_as_float(g_xbits[c * 4 + 0]);
            float x1 = __uint_as_float(g_xbits[c * 4 + 1]);
            float x2 = __uint_as_float(g_xbits[c * 4 + 2]);
            float x3 = __uint_as_float(g_xbits[c * 4 + 3]);
            float bmin = (float)((double)x0 + g_g05[c] * ((double)x1 - (double)x0));
            float bmax = (float)((double)x2 + g_g95[c] * ((double)x3 - (double)x2));
            bool ini = einit[c] != 0;
            nmin = ini ? (0.99f * emin[c] + 0.01f * bmin) : bmin;
            nmax = ini ? (0.99f * emax[c] + 0.01f * bmax) : bmax;
        }
        g_newmin[c] = nmin; g_newmax[c] = nmax;
    }
}

// ---------------- K5: gamma map + feature scaling (HBM-bound) ----------------
__global__ void k_scale(const float4* __restrict__ ft, const float* __restrict__ ranks,
                        float* __restrict__ out) {
    __shared__ float smin[CD], sinv[CD], sadd[CD], smax[CD], sint[CD];
    if (threadIdx.x < CD) {
        int c = threadIdx.x;
        float mn = g_newmin[c], mx = g_newmax[c];
        smin[c] = mn; smax[c] = mx;
        sint[c] = 1.0f - ranks[c] / 4.0f;
        if (mx > mn) { sinv[c] = 1.0f / (mx - mn + 1e-8f); sadd[c] = 0.0f; }
        else         { sinv[c] = 0.0f;                     sadd[c] = 0.5f; }
    }
    __syncthreads();
    int g = blockIdx.x * blockDim.x + threadIdx.x;
    if (g >= NG) return;
    uint4 p4 = ((const uint4*)g_packed)[g];
    unsigned pks[4] = { p4.x, p4.y, p4.z, p4.w };

    float gm[4];
#pragma unroll
    for (int k = 0; k < 4; k++) {
        unsigned pk = pks[k];
        int c = (int)(pk >> 29);
        float cv = __uint_as_float(unpack_bits(pk));
        float mn = smin[c], mx = smax[c];
        float cl = fminf(fmaxf(cv, mn), mx);
        float nr = (cl - mn) * sinv[c] + sadd[c];
        gm[k] = 1.0f + sint[c] * (1.0f + 0.5f * (1.0f - nr));
    }
    ((float4*)(out + NFEAT))[g] = make_float4(gm[0], gm[1], gm[2], gm[3]);

    int v = g * 4;
    int b = (v >= DHW) ? 1 : 0;
    int s4 = g - b * Q4;
    size_t fbase = (size_t)(b * FD) * Q4 + (size_t)s4;
    float4* o4 = (float4*)out;
#pragma unroll 8
    for (int f = 0; f < FD; f++) {
        float4 x = ft[fbase + (size_t)f * Q4];
        x.x *= gm[0]; x.y *= gm[1]; x.z *= gm[2]; x.w *= gm[3];
        o4[fbase + (size_t)f * Q4] = x;
    }
}

// ---------------- launch ----------------
extern "C" void kernel_launch(void* const* d_in, const int* in_sizes, int n_in,
                              void* d_out, int out_size) {
    const float* feat          = (const float*)d_in[0];
    const float* logits        = (const float*)d_in[1];
    const int*   labels        = (const int*)d_in[2];
    const float* ranks         = (const float*)d_in[3];
    const float* emin          = (const float*)d_in[4];
    const float* emax          = (const float*)d_in[5];
    const unsigned char* einit = (const unsigned char*)d_in[6];
    float* out = (float*)d_out;
    (void)in_sizes; (void)n_in; (void)out_size;

    k_zero<<<16, 256>>>();
    k_conf<<<296, 256>>>((const float4*)logits, (const int4*)labels);
    k_hist2<<<296, 256>>>();
    k_hist3<<<296, 256>>>();
    k_final<<<1, 640>>>(emin, emax, einit);
    k_scale<<<(NG + 255) / 256, 256>>>((const float4*)feat, ranks, out);
}

// round 6
// speedup vs baseline: 1.2460x; 1.0402x over previous
#include <cuda_runtime.h>

// Fixed problem shapes
#define BD 2
#define FD 32
#define CD 5
#define DHW 884736           // 96^3
#define Q4 (DHW/4)           // 221184
#define NVOX (BD*DHW)        // 1769472
#define NG (NVOX/4)          // 442368
#define NFEAT (BD*FD*DHW)    // 56623104
#define PLO 15872            // conf in [0.2,1.0] -> 16-bit prefix within [PLO, PLO+512)
#define NBIN 512
#define NSLOT 20             // 5 classes x 4 order statistics
#define HGRID 592            // 4 CTAs/SM on 148 SMs

// ---------------- device scratch (no allocations allowed) ----------------
__device__ __align__(16) unsigned g_packed[NVOX];   // label<<29 | (conf bits & 0x1FFFFFFF)
__device__ unsigned g_hist1[CD * NBIN];
__device__ unsigned g_hist2[NSLOT * 256];
__device__ unsigned g_hist3[NSLOT * 256];
__device__ int      g_t2_pre[NSLOT];
__device__ unsigned g_t2_rank[NSLOT];
__device__ unsigned g_n[CD];
__device__ double   g_g05[CD], g_g95[CD];
__device__ float    g_newmin[CD], g_newmax[CD];
__device__ unsigned g_done;

__device__ __forceinline__ unsigned unpack_bits(unsigned pk) {
    return (pk & 0x1FFFFFFFu) | 0x20000000u;   // restore constant top bits of conf float
}

// ---------------- K0: zero histograms + completion counter ----------------
__global__ void k_zero() {
    int i = blockIdx.x * blockDim.x + threadIdx.x;
    int stride = gridDim.x * blockDim.x;
    for (int j = i; j < CD * NBIN; j += stride) g_hist1[j] = 0;
    for (int j = i; j < NSLOT * 256; j += stride) { g_hist2[j] = 0; g_hist3[j] = 0; }
    if (i == 0) g_done = 0;
}

// ---------------- K1: confidence + packed store + level-1 histogram ----------------
__device__ __forceinline__ float conf5(float a, float b, float c, float d, float e) {
    float y0 = a * 10.0f, y1 = b * 10.0f, y2 = c * 10.0f, y3 = d * 10.0f, y4 = e * 10.0f;
    float m = fmaxf(fmaxf(fmaxf(y0, y1), fmaxf(y2, y3)), y4);
    float s = expf(y0 - m) + expf(y1 - m) + expf(y2 - m) + expf(y3 - m) + expf(y4 - m);
    return 1.0f / s;
}

__global__ void k_conf(const float4* __restrict__ lg, const int4* __restrict__ lb) {
    __shared__ unsigned sh[CD * NBIN];
    for (int j = threadIdx.x; j < CD * NBIN; j += blockDim.x) sh[j] = 0;
    __syncthreads();
    int stride = gridDim.x * blockDim.x;
    for (int g = blockIdx.x * blockDim.x + threadIdx.x; g < NG; g += stride) {
        int v = g * 4;
        int b = (v >= DHW) ? 1 : 0;
        int s4 = g - b * Q4;
        size_t base = (size_t)(b * CD) * Q4 + (size_t)s4;
        float4 L0 = __ldcs(&lg[base]);
        float4 L1 = __ldcs(&lg[base + Q4]);
        float4 L2 = __ldcs(&lg[base + 2 * (size_t)Q4]);
        float4 L3 = __ldcs(&lg[base + 3 * (size_t)Q4]);
        float4 L4 = __ldcs(&lg[base + 4 * (size_t)Q4]);
        float cf[4];
        cf[0] = conf5(L0.x, L1.x, L2.x, L3.x, L4.x);
        cf[1] = conf5(L0.y, L1.y, L2.y, L3.y, L4.y);
        cf[2] = conf5(L0.z, L1.z, L2.z, L3.z, L4.z);
        cf[3] = conf5(L0.w, L1.w, L2.w, L3.w, L4.w);
        int4 li = lb[g];
        int cc[4] = { li.x, li.y, li.z, li.w };
        unsigned pk[4];
#pragma unroll
        for (int k = 0; k < 4; k++) {
            unsigned bits = __float_as_uint(cf[k]);
            pk[k] = ((unsigned)cc[k] << 29) | (bits & 0x1FFFFFFFu);
            unsigned idx = (bits >> 16) - PLO;
            if (idx < NBIN) atomicAdd(&sh[cc[k] * NBIN + idx], 1u);
        }
        ((uint4*)g_packed)[g] = make_uint4(pk[0], pk[1], pk[2], pk[3]);
    }
    __syncthreads();
    for (int j = threadIdx.x; j < CD * NBIN; j += blockDim.x) {
        unsigned u = sh[j];
        if (u) atomicAdd(&g_hist1[j], u);
    }
}

// ---------------- K2: fused find2 prologue + level-2 histogram ----------------
__global__ void k_hist2() {
    __shared__ unsigned shh[NSLOT * 256];
    __shared__ int      spre[NSLOT];
    __shared__ unsigned srank[NSLOT];
    __shared__ int      sskip[NSLOT];
    __shared__ unsigned swsum[8], swpre[8];
    __shared__ unsigned s_n;

    int t = threadIdx.x, lane = t & 31, warp = t >> 5;
    if (t < NSLOT) { spre[t] = -1; srank[t] = 0; }
    __syncthreads();

    // ---- find2: per-class scan of the 512-bin prefix histogram (recomputed per block) ----
    for (int c = 0; c < CD; c++) {
        unsigned a = g_hist1[c * NBIN + 2 * t];
        unsigned b = g_hist1[c * NBIN + 2 * t + 1];
        unsigned s = a + b;
        unsigned incl = s;
        for (int off = 1; off < 32; off <<= 1) {
            unsigned u = __shfl_up_sync(0xffffffffu, incl, off);
            if (lane >= off) incl += u;
        }
        if (lane == 31) swsum[warp] = incl;
        __syncthreads();
        if (t == 0) {
            unsigned run = 0;
#pragma unroll
            for (int w = 0; w < 8; w++) { swpre[w] = run; run += swsum[w]; }
            s_n = run;
        }
        __syncthreads();
        unsigned total = s_n;
        long long exclp = (long long)(incl - s + swpre[warp]);
        long long n = (long long)total;
        if (n == 0) {
            if (t == 0 && blockIdx.x == 0) { g_n[c] = 0; g_g05[c] = 0.0; g_g95[c] = 0.0; }
        } else {
            double p05 = 0.05 * (double)(n - 1);
            long long i05 = (long long)p05;
            double p95 = 0.95 * (double)(n - 1);
            long long i95 = (long long)p95;
            if (t == 0 && blockIdx.x == 0) {
                g_n[c] = total;
                g_g05[c] = p05 - (double)i05;
                g_g95[c] = p95 - (double)i95;
            }
            long long rr[4];
            rr[0] = i05; rr[1] = (i05 + 1 < n) ? i05 + 1 : i05;
            rr[2] = i95; rr[3] = (i95 + 1 < n) ? i95 + 1 : i95;
#pragma unroll
            for (int j = 0; j < 4; j++) {
                long long r = rr[j];
                if (r >= exclp && r < exclp + (long long)s) {
                    unsigned rem = (unsigned)(r - exclp);
                    if (rem < a) { spre[c * 4 + j] = PLO + 2 * t;     srank[c * 4 + j] = rem; }
                    else         { spre[c * 4 + j] = PLO + 2 * t + 1; srank[c * 4 + j] = rem - a; }
                }
            }
        }
        __syncthreads();
    }
    if (t < NSLOT) {
        sskip[t] = ((t & 1) && spre[t] >= 0 && spre[t] == spre[t - 1]) ? 1 : 0;
        if (blockIdx.x == 0) { g_t2_pre[t] = spre[t]; g_t2_rank[t] = srank[t]; }
    }
    for (int j = t; j < NSLOT * 256; j += blockDim.x) shh[j] = 0;
    __syncthreads();

    // ---- level-2 histogram over packed stream ----
    int stride = gridDim.x * blockDim.x;
    for (int g = blockIdx.x * blockDim.x + t; g < NG; g += stride) {
        uint4 p4 = ((const uint4*)g_packed)[g];
        unsigned pks[4] = { p4.x, p4.y, p4.z, p4.w };
#pragma unroll
        for (int k = 0; k < 4; k++) {
            unsigned pk = pks[k];
            int c = (int)(pk >> 29);
            unsigned bits = unpack_bits(pk);
            int p = (int)(bits >> 16);
            int b1 = (int)((bits >> 8) & 255u);
            int base = c * 4;
#pragma unroll
            for (int s = 0; s < 4; s++) {
                int slot = base + s;
                if (!sskip[slot] && spre[slot] == p) atomicAdd(&shh[slot * 256 + b1], 1u);
            }
        }
    }
    __syncthreads();
    for (int j = t; j < NSLOT * 256; j += blockDim.x) {
        unsigned u = shh[j];
        if (u) atomicAdd(&g_hist2[j], u);
    }
}

// ---------------- K3: fused find3 prologue + level-3 histogram + last-block finalize ----
__global__ void k_hist3(const float* __restrict__ emin, const float* __restrict__ emax,
                        const unsigned char* __restrict__ einit) {
    __shared__ unsigned shh[NSLOT * 256];
    __shared__ int      sp[NSLOT];
    __shared__ int      sb[NSLOT];
    __shared__ unsigned sr[NSLOT];
    __shared__ int      sskip[NSLOT];
    __shared__ unsigned sx[NSLOT];
    __shared__ bool     is_last;

    int t = threadIdx.x, lane = t & 31, warp = t >> 5;
    if (t < NSLOT) { sp[t] = g_t2_pre[t]; sb[t] = -1; sr[t] = 0; }
    __syncthreads();

    // ---- find3: warp per slot, locate byte[15:8] (recomputed per block) ----
    for (int slot = warp; slot < NSLOT; slot += 8) {
        int pre = sp[slot];
        if (pre < 0) continue;
        int src = slot;
        if ((slot & 1) && pre == sp[slot - 1]) src = slot - 1;
        unsigned rank = g_t2_rank[slot];
        unsigned h[8]; unsigned sum = 0;
#pragma unroll
        for (int j = 0; j < 8; j++) { h[j] = g_hist2[src * 256 + lane * 8 + j]; sum += h[j]; }
        unsigned v = sum;
        for (int off = 1; off < 32; off <<= 1) {
            unsigned u = __shfl_up_sync(0xffffffffu, v, off);
            if (lane >= off) v += u;
        }
        unsigned excl = v - sum;
        if (excl <= rank && rank < excl + sum) {
            unsigned run = excl;
#pragma unroll
            for (int j = 0; j < 8; j++) {
                if (rank < run + h[j]) { sb[slot] = lane * 8 + j; sr[slot] = rank - run; break; }
                run += h[j];
            }
        }
    }
    __syncthreads();
    if (t < NSLOT)
        sskip[t] = ((t & 1) && sp[t] >= 0 && sp[t] == sp[t - 1] && sb[t] == sb[t - 1]) ? 1 : 0;
    for (int j = t; j < NSLOT * 256; j += blockDim.x) shh[j] = 0;
    __syncthreads();

    // ---- level-3 histogram ----
    int stride = gridDim.x * blockDim.x;
    for (int g = blockIdx.x * blockDim.x + t; g < NG; g += stride) {
        uint4 p4 = ((const uint4*)g_packed)[g];
        unsigned pks[4] = { p4.x, p4.y, p4.z, p4.w };
#pragma unroll
        for (int k = 0; k < 4; k++) {
            unsigned pk = pks[k];
            int c = (int)(pk >> 29);
            unsigned bits = unpack_bits(pk);
            int p = (int)(bits >> 16);
            int b1 = (int)((bits >> 8) & 255u);
            int b0 = (int)(bits & 255u);
            int base = c * 4;
#pragma unroll
            for (int s = 0; s < 4; s++) {
                int slot = base + s;
                if (!sskip[slot] && sp[slot] == p && sb[slot] == b1) atomicAdd(&shh[slot * 256 + b0], 1u);
            }
        }
    }
    __syncthreads();
    for (int j = t; j < NSLOT * 256; j += blockDim.x) {
        unsigned u = shh[j];
        if (u) atomicAdd(&g_hist3[j], u);
    }

    // ---- last-block finalize: exact order statistics -> quantiles -> EMA ----
    __threadfence();
    if (t == 0) is_last = (atomicAdd(&g_done, 1u) == (unsigned)(gridDim.x - 1));
    __syncthreads();
    if (!is_last) return;

    for (int slot = warp; slot < NSLOT; slot += 8) {
        int pre = sp[slot];
        if (pre < 0) continue;
        int byt = sb[slot];
        int src = slot;
        if ((slot & 1) && pre == sp[slot - 1] && byt == sb[slot - 1]) src = slot - 1;
        unsigned rank = sr[slot];
        unsigned h[8]; unsigned sum = 0;
#pragma unroll
        for (int j = 0; j < 8; j++) { h[j] = g_hist3[src * 256 + lane * 8 + j]; sum += h[j]; }
        unsigned v = sum;
        for (int off = 1; off < 32; off <<= 1) {
            unsigned u = __shfl_up_sync(0xffffffffu, v, off);
            if (lane >= off) v += u;
        }
        unsigned excl = v - sum;
        if (excl <= rank && rank < excl + sum) {
            unsigned run = excl;
#pragma unroll
            for (int j = 0; j < 8; j++) {
                if (rank < run + h[j]) {
                    sx[slot] = ((unsigned)pre << 16) | ((unsigned)byt << 8) | (unsigned)(lane * 8 + j);
                    break;
                }
                run += h[j];
            }
        }
    }
    __syncthreads();
    if (t < CD) {
        int c = t;
        float nmin, nmax;
        if (g_n[c] == 0) {
            nmin = emin[c]; nmax = emax[c];
        } else {
            float x0 = __uint_as_float(sx[c * 4 + 0]);
            float x1 = __uint_as_float(sx[c * 4 + 1]);
            float x2 = __uint_as_float(sx[c * 4 + 2]);
            float x3 = __uint_as_float(sx[c * 4 + 3]);
            float bmin = (float)((double)x0 + g_g05[c] * ((double)x1 - (double)x0));
            float bmax = (float)((double)x2 + g_g95[c] * ((double)x3 - (double)x2));
            bool ini = einit[c] != 0;
            nmin = ini ? (0.99f * emin[c] + 0.01f * bmin) : bmin;
            nmax = ini ? (0.99f * emax[c] + 0.01f * bmax) : bmax;
        }
        g_newmin[c] = nmin; g_newmax[c] = nmax;
    }
}

// ---------------- K4: gamma map + feature scaling (HBM-bound) ----------------
__global__ void k_scale(const float4* __restrict__ ft, const float* __restrict__ ranks,
                        float* __restrict__ out) {
    __shared__ float smin[CD], sinv[CD], sadd[CD], smax[CD], sint[CD];
    if (threadIdx.x < CD) {
        int c = threadIdx.x;
        float mn = g_newmin[c], mx = g_newmax[c];
        smin[c] = mn; smax[c] = mx;
        sint[c] = 1.0f - ranks[c] / 4.0f;
        if (mx > mn) { sinv[c] = 1.0f / (mx - mn + 1e-8f); sadd[c] = 0.0f; }
        else         { sinv[c] = 0.0f;                     sadd[c] = 0.5f; }
    }
    __syncthreads();
    int g = blockIdx.x * blockDim.x + threadIdx.x;
    if (g >= NG) return;
    uint4 p4 = ((const uint4*)g_packed)[g];
    unsigned pks[4] = { p4.x, p4.y, p4.z, p4.w };

    float gm[4];
#pragma unroll
    for (int k = 0; k < 4; k++) {
        unsigned pk = pks[k];
        int c = (int)(pk >> 29);
        float cv = __uint_as_float(unpack_bits(pk));
        float mn = smin[c], mx = smax[c];
        float cl = fminf(fmaxf(cv, mn), mx);
        float nr = (cl - mn) * sinv[c] + sadd[c];
        gm[k] = 1.0f + sint[c] * (1.0f + 0.5f * (1.0f - nr));
    }
    __stcs((float4*)(out + NFEAT) + g, make_float4(gm[0], gm[1], gm[2], gm[3]));

    int v = g * 4;
    int b = (v >= DHW) ? 1 : 0;
    int s4 = g - b * Q4;
    size_t fbase = (size_t)(b * FD) * Q4 + (size_t)s4;
    float4* o4 = (float4*)out;
#pragma unroll 8
    for (int f = 0; f < FD; f++) {
        float4 x = __ldcs(&ft[fbase + (size_t)f * Q4]);
        x.x *= gm[0]; x.y *= gm[1]; x.z *= gm[2]; x.w *= gm[3];
        __stcs(&o4[fbase + (size_t)f * Q4], x);
    }
}

// ---------------- launch ----------------
extern "C" void kernel_launch(void* const* d_in, const int* in_sizes, int n_in,
                              void* d_out, int out_size) {
    const float* feat          = (const float*)d_in[0];
    const float* logits        = (const float*)d_in[1];
    const int*   labels        = (const int*)d_in[2];
    const float* ranks         = (const float*)d_in[3];
    const float* emin          = (const float*)d_in[4];
    const float* emax          = (const float*)d_in[5];
    const unsigned char* einit = (const unsigned char*)d_in[6];
    float* out = (float*)d_out;
    (void)in_sizes; (void)n_in; (void)out_size;

    k_zero<<<16, 256>>>();
    k_conf<<<HGRID, 256>>>((const float4*)logits, (const int4*)labels);
    k_hist2<<<HGRID, 256>>>();
    k_hist3<<<HGRID, 256>>>(emin, emax, einit);
    k_scale<<<(NG + 255) / 256, 256>>>((const float4*)feat, ranks, out);
}